// round 10
// baseline (speedup 1.0000x reference)
#include <cuda_runtime.h>
#include <cuda_bf16.h>

#define W_IN 160
#define H_IN 160
#define HW   (H_IN * W_IN)
#define C_IN 256
#define CB   128                   // channels per block
#define POOLED 7
#define MAXT 5                     // max footprint side (3*sw <= 2.16 => <=5)
#define MAXSTRIDE 25

__device__ __forceinline__ void cp_async4(float* smem_dst, const float* gmem_src) {
    unsigned s = (unsigned)__cvta_generic_to_shared(smem_dst);
    asm volatile("cp.async.ca.shared.global [%0], [%1], 4;\n" :: "r"(s), "l"(gmem_src));
}

struct Geo {
    float wstart, hstart;
    int xlo, ylo, w, h, area, stride;
};

__global__ __launch_bounds__(CB, 8)
void dcnv2_pool_kernel(const float* __restrict__ inp,
                       const float* __restrict__ rois,
                       const float* __restrict__ offset,
                       float* __restrict__ out,
                       int N)
{
    __shared__ float bufA[CB * MAXSTRIDE];       // 12.8 KB
    __shared__ float bufB[CB * MAXSTRIDE];       // 12.8 KB

    const int ph   = blockIdx.x >> 2;            // 0..6
    const int pair = blockIdx.x & 3;             // 0..3
    const int pwA  = pair * 2;                   // 0,2,4,6
    const bool hasB = (pair < 3);
    const int pwB  = hasB ? pwA + 1 : pwA;
    const int n    = blockIdx.y;
    const int ch0  = blockIdx.z * CB;
    const int tid  = threadIdx.x;                // 0..127 (= local channel)
    const int lane = tid & 31;
    const int warp = tid >> 5;

    // ---- ROI geometry (bin-independent; uniform) ----
    const float* roi = rois + n * 5;
    const int   b  = (int)__ldg(&roi[0]);
    const float rsw = rintf(__ldg(&roi[1])) * 0.0625f - 0.5f;
    const float rsh = rintf(__ldg(&roi[2])) * 0.0625f - 0.5f;
    const float rew = (rintf(__ldg(&roi[3])) + 1.0f) * 0.0625f - 0.5f;
    const float reh = (rintf(__ldg(&roi[4])) + 1.0f) * 0.0625f - 0.5f;
    const float rw  = fmaxf(rew - rsw, 0.1f);
    const float rh  = fmaxf(reh - rsh, 0.1f);
    const float bw  = rw * (1.0f / 7.0f);
    const float bh  = rh * (1.0f / 7.0f);
    const float sw  = bw * 0.25f;
    const float sh  = bh * 0.25f;

    const float* img  = inp + (size_t)b * (C_IN * HW) + (size_t)(ch0 + warp * 32) * HW;
    const float* offp = offset + ((n * 2) * POOLED + ph) * POOLED;

    auto geo = [&](int pw, Geo& g) {
        const float tx = __ldg(&offp[pw])      * 0.1f;
        const float ty = __ldg(&offp[49 + pw]) * 0.1f;
        g.wstart = pw * bw + rsw + tx * rw;
        g.hstart = ph * bh + rsh + ty * rh;
        const float xcA = fminf(fmaxf(g.wstart,             0.0f), (float)(W_IN - 1));
        const float xcB = fminf(fmaxf(g.wstart + 3.0f * sw, 0.0f), (float)(W_IN - 1));
        const float ycA = fminf(fmaxf(g.hstart,             0.0f), (float)(H_IN - 1));
        const float ycB = fminf(fmaxf(g.hstart + 3.0f * sh, 0.0f), (float)(H_IN - 1));
        g.xlo = (int)floorf(xcA);
        g.ylo = (int)floorf(ycA);
        g.w   = min((int)ceilf(xcB) - g.xlo + 1, MAXT);   // 1..5, fully in-image
        g.h   = min((int)ceilf(ycB) - g.ylo + 1, MAXT);
        g.area   = g.w * g.h;
        g.stride = g.area | 1;                            // odd -> conflict-free
    };

    auto stage = [&](const Geo& g, float* buf) {
        if (lane < g.area) {
            const int yy = lane / g.w;
            const int xx = lane - yy * g.w;
            const float* gp = img + (g.ylo + yy) * W_IN + (g.xlo + xx);
            float* sp = buf + (warp * 32) * g.stride + lane;
            #pragma unroll
            for (int i = 0; i < 32; i++) {
                cp_async4(sp, gp);
                gp += HW;
                sp += g.stride;
            }
        }
        asm volatile("cp.async.commit_group;\n" ::: "memory");
    };

    // Per-thread separable weights (R8-proven): also serves as wait filler.
    auto weights = [&](const Geo& g, float* WX, float* WY, float& cnt) {
        #pragma unroll
        for (int e = 0; e < MAXT; e++) { WX[e] = 0.0f; WY[e] = 0.0f; }
        float cntX = 0.0f, cntY = 0.0f;
        #pragma unroll
        for (int s = 0; s < 4; s++) {
            const float x   = g.wstart + (float)s * sw;
            const float okx = (x >= -0.5f && x <= (float)W_IN - 0.5f) ? 1.0f : 0.0f;
            const float xc  = fminf(fmaxf(x, 0.0f), (float)(W_IN - 1));
            cntX += okx;
            #pragma unroll
            for (int e = 0; e < MAXT; e++)
                WX[e] += okx * fmaxf(1.0f - fabsf(xc - (float)(g.xlo + e)), 0.0f);

            const float y   = g.hstart + (float)s * sh;
            const float oky = (y >= -0.5f && y <= (float)H_IN - 0.5f) ? 1.0f : 0.0f;
            const float yc  = fminf(fmaxf(y, 0.0f), (float)(H_IN - 1));
            cntY += oky;
            #pragma unroll
            for (int e = 0; e < MAXT; e++)
                WY[e] += oky * fmaxf(1.0f - fabsf(yc - (float)(g.ylo + e)), 0.0f);
        }
        cnt = cntX * cntY;
    };

    auto dot = [&](const Geo& g, const float* buf, const float* WX, const float* WY) {
        const float* tch = buf + tid * g.stride;
        float acc = 0.0f;
        #pragma unroll
        for (int yy = 0; yy < MAXT; yy++) {
            if (yy < g.h) {
                float r = 0.0f;
                #pragma unroll
                for (int xx = 0; xx < MAXT; xx++) {
                    if (xx < g.w) r += WX[xx] * tch[yy * g.w + xx];
                }
                acc += WY[yy] * r;
            }
        }
        return acc;
    };

    // ---- pipeline: stage A, stage B, weights A, wait A, dot A, weights B, wait B, dot B
    Geo gA, gB;
    geo(pwA, gA);
    stage(gA, bufA);                               // group G0
    if (hasB) {
        geo(pwB, gB);
        stage(gB, bufB);                           // group G1
    }

    float WXa[MAXT], WYa[MAXT], cntA;
    weights(gA, WXa, WYa, cntA);                   // overlaps both groups' flight

    if (hasB) { asm volatile("cp.async.wait_group 1;\n" ::: "memory"); }
    else      { asm volatile("cp.async.wait_group 0;\n" ::: "memory"); }
    __syncwarp();                                  // staging is warp-local

    const float accA = dot(gA, bufA, WXa, WYa);
    out[(((size_t)n * C_IN + ch0 + tid) * POOLED + ph) * POOLED + pwA] =
        accA / fmaxf(cntA, 1.0f);

    if (hasB) {
        float WXb[MAXT], WYb[MAXT], cntB;
        weights(gB, WXb, WYb, cntB);               // overlaps G1's remaining flight
        asm volatile("cp.async.wait_group 0;\n" ::: "memory");
        __syncwarp();
        const float accB = dot(gB, bufB, WXb, WYb);
        out[(((size_t)n * C_IN + ch0 + tid) * POOLED + ph) * POOLED + pwB] =
            accB / fmaxf(cntB, 1.0f);
    }
}

extern "C" void kernel_launch(void* const* d_in, const int* in_sizes, int n_in,
                              void* d_out, int out_size)
{
    const float* inp    = (const float*)d_in[0];   // (2, 256, 160, 160) f32
    const float* rois   = (const float*)d_in[1];   // (N, 5) f32
    const float* offset = (const float*)d_in[2];   // (N, 2, 7, 7) f32
    float* out = (float*)d_out;                    // (N, 256, 7, 7) f32

    const int N = in_sizes[1] / 5;

    dim3 grid(28, N, C_IN / CB);                   // (7 ph x 4 pairs) x N x 2
    dim3 block(CB);                                // 128 threads
    dcnv2_pool_kernel<<<grid, block>>>(inp, rois, offset, out, N);
}